// round 1
// baseline (speedup 1.0000x reference)
#include <cuda_runtime.h>
#include <cuda_bf16.h>

// Problem constants
#define BB 2
#define TT 2048
#define DD 1024
#define HH 16
#define DH 64
#define MROWS (BB*TT)      // 4096

// Scratch (device globals — no allocation allowed)
__device__ float g_Q[(size_t)BB*HH*TT*DH];   // [B,H,T,dh]
__device__ float g_K[(size_t)BB*HH*TT*DH];
__device__ float g_V[(size_t)BB*HH*TT*DH];
__device__ float g_A[(size_t)MROWS*DD];      // [B,T,D] attention output

// ---------------------------------------------------------------------------
// Kernel 1: QKV GEMM.  C[4096,3072] = X[4096,1024] @ W[1024,3072] + bias,
// scattered into g_Q/g_K/g_V in [B,H,T,dh] layout.
// 128x128 tile, BK=16, 256 threads, 8x8 per-thread microtile.
// ---------------------------------------------------------------------------
__global__ __launch_bounds__(256) void gemm_qkv(const float* __restrict__ X,
                                                const float* __restrict__ W,
                                                const float* __restrict__ bias) {
    const int K = DD, N = 3*DD;
    __shared__ float As[16*128];   // As[k][m] (transposed)
    __shared__ float Bs[16*128];   // Bs[k][n]

    int m0 = blockIdx.y * 128;
    int n0 = blockIdx.x * 128;
    int tid = threadIdx.x;
    int tx = tid & 15, ty = tid >> 4;

    float acc[8][8];
#pragma unroll
    for (int i = 0; i < 8; i++)
#pragma unroll
        for (int j = 0; j < 8; j++) acc[i][j] = 0.f;

    int a_row = tid >> 2;         // 0..63
    int a_c4  = (tid & 3) * 4;    // 0,4,8,12
    int b_kr  = tid >> 5;         // 0..7
    int b_c4  = (tid & 31) * 4;   // 0..124

    for (int k0 = 0; k0 < K; k0 += 16) {
#pragma unroll
        for (int r = 0; r < 2; r++) {
            int row = a_row + r*64;
            float4 v = *(const float4*)&X[(size_t)(m0+row)*K + k0 + a_c4];
            As[(a_c4+0)*128 + row] = v.x;
            As[(a_c4+1)*128 + row] = v.y;
            As[(a_c4+2)*128 + row] = v.z;
            As[(a_c4+3)*128 + row] = v.w;
        }
#pragma unroll
        for (int r = 0; r < 2; r++) {
            int kr = b_kr + r*8;
            float4 v = *(const float4*)&W[(size_t)(k0+kr)*N + n0 + b_c4];
            *(float4*)&Bs[kr*128 + b_c4] = v;
        }
        __syncthreads();
#pragma unroll
        for (int k = 0; k < 16; k++) {
            float a[8], b[8];
            *(float4*)&a[0] = *(const float4*)&As[k*128 + ty*8];
            *(float4*)&a[4] = *(const float4*)&As[k*128 + ty*8 + 4];
            *(float4*)&b[0] = *(const float4*)&Bs[k*128 + tx*8];
            *(float4*)&b[4] = *(const float4*)&Bs[k*128 + tx*8 + 4];
#pragma unroll
            for (int i = 0; i < 8; i++)
#pragma unroll
                for (int j = 0; j < 8; j++)
                    acc[i][j] += a[i]*b[j];
        }
        __syncthreads();
    }

    // Scatter epilogue into Q/K/V [B,H,T,dh]
#pragma unroll
    for (int i = 0; i < 8; i++) {
        int m = m0 + ty*8 + i;
        int bb = m >> 11;            // /2048
        int t  = m & 2047;
#pragma unroll
        for (int j = 0; j < 8; j++) {
            int n = n0 + tx*8 + j;
            float v = acc[i][j] + bias[n];
            int sel = n >> 10;       // 0=q,1=k,2=v
            int r   = n & 1023;
            int h   = r >> 6;
            int dd  = r & 63;
            float* dst = (sel == 0) ? g_Q : (sel == 1 ? g_K : g_V);
            dst[((size_t)(bb*HH + h)*TT + t)*DH + dd] = v;
        }
    }
}

// ---------------------------------------------------------------------------
// Kernel 2: causal flash attention, fp32.
// grid = (T/64, B*H); block = 256; 64 query rows per CTA; 64-key tiles.
// ---------------------------------------------------------------------------
__global__ __launch_bounds__(256) void attn_kernel() {
    extern __shared__ float sm[];
    const int P = 65;              // smem pitch
    float* Qs = sm;                // [64][P]
    float* Ks = sm + 64*P;
    float* Vs = sm + 2*64*P;
    float* Ps = sm + 3*64*P;

    int tid = threadIdx.x;
    int tx = tid & 15, ty = tid >> 4;
    int qt = blockIdx.x, bh = blockIdx.y;
    int q0 = qt * 64;

    const float* Qp = g_Q + (size_t)bh * (TT*DH);
    const float* Kp = g_K + (size_t)bh * (TT*DH);
    const float* Vp = g_V + (size_t)bh * (TT*DH);

    int lrow = tid >> 4;           // 0..15
    int lcol = (tid & 15) * 4;     // 0..60

    // Load Q tile
#pragma unroll
    for (int r = 0; r < 4; r++) {
        int row = r*16 + lrow;
        float4 v = *(const float4*)&Qp[(size_t)(q0+row)*DH + lcol];
        Qs[row*P + lcol + 0] = v.x;
        Qs[row*P + lcol + 1] = v.y;
        Qs[row*P + lcol + 2] = v.z;
        Qs[row*P + lcol + 3] = v.w;
    }

    float m_i[4], l_i[4], o[4][4];
#pragma unroll
    for (int i = 0; i < 4; i++) {
        m_i[i] = -1e30f; l_i[i] = 0.f;
#pragma unroll
        for (int j = 0; j < 4; j++) o[i][j] = 0.f;
    }

    int r0 = ty*4, c0 = tx*4;
    const float scale = 0.125f;    // 1/sqrt(64)

    for (int jt = 0; jt <= qt; jt++) {
        __syncthreads();           // prev-iter PV done; Q stores visible on first iter
        int k0g = jt*64;
#pragma unroll
        for (int r = 0; r < 4; r++) {
            int row = r*16 + lrow;
            float4 kv = *(const float4*)&Kp[(size_t)(k0g+row)*DH + lcol];
            Ks[row*P + lcol + 0] = kv.x;
            Ks[row*P + lcol + 1] = kv.y;
            Ks[row*P + lcol + 2] = kv.z;
            Ks[row*P + lcol + 3] = kv.w;
            float4 vv = *(const float4*)&Vp[(size_t)(k0g+row)*DH + lcol];
            Vs[row*P + lcol + 0] = vv.x;
            Vs[row*P + lcol + 1] = vv.y;
            Vs[row*P + lcol + 2] = vv.z;
            Vs[row*P + lcol + 3] = vv.w;
        }
        __syncthreads();

        // S = Q K^T (4x4 per thread)
        float s[4][4];
#pragma unroll
        for (int i = 0; i < 4; i++)
#pragma unroll
            for (int j = 0; j < 4; j++) s[i][j] = 0.f;
#pragma unroll 8
        for (int k = 0; k < 64; k++) {
            float qv[4], kv[4];
#pragma unroll
            for (int i = 0; i < 4; i++) qv[i] = Qs[(r0+i)*P + k];
#pragma unroll
            for (int j = 0; j < 4; j++) kv[j] = Ks[(c0+j)*P + k];
#pragma unroll
            for (int i = 0; i < 4; i++)
#pragma unroll
                for (int j = 0; j < 4; j++)
                    s[i][j] += qv[i]*kv[j];
        }

        bool diag = (jt == qt);
#pragma unroll
        for (int i = 0; i < 4; i++) {
#pragma unroll
            for (int j = 0; j < 4; j++) {
                s[i][j] *= scale;
                if (diag && (c0+j) > (r0+i)) s[i][j] = -1e30f;
            }
            // row max across 16 lanes (half-warp group)
            float mx = fmaxf(fmaxf(s[i][0], s[i][1]), fmaxf(s[i][2], s[i][3]));
#pragma unroll
            for (int off = 1; off < 16; off <<= 1)
                mx = fmaxf(mx, __shfl_xor_sync(0xffffffffu, mx, off));
            float mnew = fmaxf(m_i[i], mx);
            float corr = __expf(m_i[i] - mnew);
            float rs = 0.f;
#pragma unroll
            for (int j = 0; j < 4; j++) {
                s[i][j] = __expf(s[i][j] - mnew);
                rs += s[i][j];
            }
#pragma unroll
            for (int off = 1; off < 16; off <<= 1)
                rs += __shfl_xor_sync(0xffffffffu, rs, off);
            l_i[i] = l_i[i]*corr + rs;
            m_i[i] = mnew;
#pragma unroll
            for (int j = 0; j < 4; j++) {
                o[i][j] *= corr;
                Ps[(r0+i)*P + c0 + j] = s[i][j];
            }
        }
        __syncthreads();

        // O += P @ V
#pragma unroll 8
        for (int k = 0; k < 64; k++) {
            float pv[4], vv[4];
#pragma unroll
            for (int i = 0; i < 4; i++) pv[i] = Ps[(r0+i)*P + k];
#pragma unroll
            for (int j = 0; j < 4; j++) vv[j] = Vs[k*P + c0 + j];
#pragma unroll
            for (int i = 0; i < 4; i++)
#pragma unroll
                for (int j = 0; j < 4; j++)
                    o[i][j] += pv[i]*vv[j];
        }
    }

    // Write [B,T,H,dh] (== merged [B,T,D])
    int bb = bh >> 4, h = bh & 15;
#pragma unroll
    for (int i = 0; i < 4; i++) {
        float inv = 1.0f / l_i[i];
        int t = q0 + r0 + i;
#pragma unroll
        for (int j = 0; j < 4; j++)
            g_A[((size_t)(bb*TT + t)*HH + h)*DH + c0 + j] = o[i][j] * inv;
    }
}

// ---------------------------------------------------------------------------
// Kernel 3: output projection.  out[4096,1024] = A @ W_proj + b_proj
// ---------------------------------------------------------------------------
__global__ __launch_bounds__(256) void gemm_proj(const float* __restrict__ W,
                                                 const float* __restrict__ bias,
                                                 float* __restrict__ out) {
    const int K = DD, N = DD;
    __shared__ float As[16*128];
    __shared__ float Bs[16*128];

    int m0 = blockIdx.y * 128;
    int n0 = blockIdx.x * 128;
    int tid = threadIdx.x;
    int tx = tid & 15, ty = tid >> 4;

    float acc[8][8];
#pragma unroll
    for (int i = 0; i < 8; i++)
#pragma unroll
        for (int j = 0; j < 8; j++) acc[i][j] = 0.f;

    int a_row = tid >> 2;
    int a_c4  = (tid & 3) * 4;
    int b_kr  = tid >> 5;
    int b_c4  = (tid & 31) * 4;

    for (int k0 = 0; k0 < K; k0 += 16) {
#pragma unroll
        for (int r = 0; r < 2; r++) {
            int row = a_row + r*64;
            float4 v = *(const float4*)&g_A[(size_t)(m0+row)*K + k0 + a_c4];
            As[(a_c4+0)*128 + row] = v.x;
            As[(a_c4+1)*128 + row] = v.y;
            As[(a_c4+2)*128 + row] = v.z;
            As[(a_c4+3)*128 + row] = v.w;
        }
#pragma unroll
        for (int r = 0; r < 2; r++) {
            int kr = b_kr + r*8;
            float4 v = *(const float4*)&W[(size_t)(k0+kr)*N + n0 + b_c4];
            *(float4*)&Bs[kr*128 + b_c4] = v;
        }
        __syncthreads();
#pragma unroll
        for (int k = 0; k < 16; k++) {
            float a[8], b[8];
            *(float4*)&a[0] = *(const float4*)&As[k*128 + ty*8];
            *(float4*)&a[4] = *(const float4*)&As[k*128 + ty*8 + 4];
            *(float4*)&b[0] = *(const float4*)&Bs[k*128 + tx*8];
            *(float4*)&b[4] = *(const float4*)&Bs[k*128 + tx*8 + 4];
#pragma unroll
            for (int i = 0; i < 8; i++)
#pragma unroll
                for (int j = 0; j < 8; j++)
                    acc[i][j] += a[i]*b[j];
        }
        __syncthreads();
    }

#pragma unroll
    for (int i = 0; i < 8; i++) {
        int m = m0 + ty*8 + i;
#pragma unroll
        for (int j = 0; j < 8; j++) {
            int n = n0 + tx*8 + j;
            out[(size_t)m*N + n] = acc[i][j] + bias[n];
        }
    }
}

// ---------------------------------------------------------------------------
extern "C" void kernel_launch(void* const* d_in, const int* in_sizes, int n_in,
                              void* d_out, int out_size) {
    const float* x      = (const float*)d_in[0];
    const float* W_attn = (const float*)d_in[1];
    const float* b_attn = (const float*)d_in[2];
    const float* W_proj = (const float*)d_in[3];
    const float* b_proj = (const float*)d_in[4];
    float* out = (float*)d_out;

    // QKV projection: grid (N/128=24, M/128=32)
    gemm_qkv<<<dim3(24, 32), 256>>>(x, W_attn, b_attn);

    // Flash attention: dynamic smem 4 * 64*65 floats
    int smem = 4 * 64 * 65 * (int)sizeof(float);
    cudaFuncSetAttribute(attn_kernel, cudaFuncAttributeMaxDynamicSharedMemorySize, smem);
    attn_kernel<<<dim3(TT/64, BB*HH), 256, smem>>>();

    // Output projection: grid (8, 32)
    gemm_proj<<<dim3(8, 32), 256>>>(W_proj, b_proj, out);
}

// round 7
// speedup vs baseline: 2.6664x; 2.6664x over previous
#include <cuda_runtime.h>
#include <cuda_bf16.h>
#include <cstdint>

// Problem constants
#define BB 2
#define TT 2048
#define DD 1024
#define HH 16
#define DH 64
#define MROWS (BB*TT)      // 4096

// Scratch (device globals — no allocation allowed)
__device__ float g_Q[(size_t)BB*HH*TT*DH];   // [B,H,T,dh]
__device__ float g_K[(size_t)BB*HH*TT*DH];
__device__ float g_V[(size_t)BB*HH*TT*DH];
__device__ float g_A[(size_t)MROWS*DD];      // [B,T,D] attention output

// ---------------------------------------------------------------------------
// tf32 helpers
// ---------------------------------------------------------------------------
__device__ __forceinline__ uint32_t f2tf32(float f) {
    uint32_t r;
    asm("cvt.rna.tf32.f32 %0, %1;" : "=r"(r) : "f"(f));
    return r;
}

__device__ __forceinline__ void mma_tf32(float* c, const uint32_t* a, const uint32_t* b) {
    asm volatile(
        "mma.sync.aligned.m16n8k8.row.col.f32.tf32.tf32.f32 "
        "{%0,%1,%2,%3}, {%4,%5,%6,%7}, {%8,%9}, {%0,%1,%2,%3};"
        : "+f"(c[0]), "+f"(c[1]), "+f"(c[2]), "+f"(c[3])
        : "r"(a[0]), "r"(a[1]), "r"(a[2]), "r"(a[3]),
          "r"(b[0]), "r"(b[1]));
}

__device__ __forceinline__ void qkv_store(int m, int n, float v) {
    int bb = m >> 11, t = m & 2047;
    int sel = n >> 10;            // 0=q,1=k,2=v
    int r   = n & 1023;
    int h   = r >> 6;
    int dd  = r & 63;
    float* dst = (sel == 0) ? g_Q : (sel == 1 ? g_K : g_V);
    dst[((size_t)(bb*HH + h)*TT + t)*DH + dd] = v;
}

// ---------------------------------------------------------------------------
// tf32 tensor-core GEMM:  C[M=4096, NCOLS] = A[4096,1024] @ W[1024,NCOLS] + bias
// MODE 1: QKV (A = x input, scatter epilogue into g_Q/g_K/g_V)
// MODE 0: proj (A = g_A, plain epilogue into out)
// 128x128x32 CTA tile, 256 threads (8 warps, 2x4), warp tile 64x32.
// ---------------------------------------------------------------------------
template<int NCOLS, int MODE>
__global__ __launch_bounds__(256) void gemm_tf32(const float* __restrict__ Ain,
                                                 const float* __restrict__ W,
                                                 const float* __restrict__ bias,
                                                 float* __restrict__ out) {
    const int K = DD;
    const int PIT = 136;                     // smem pitch: bank = 8*tig+gid (unique)
    __shared__ uint32_t As[32*PIT];          // [k][m], tf32 bits
    __shared__ uint32_t Bs[32*PIT];          // [k][n], tf32 bits

    const float* Ap = (MODE == 1) ? Ain : g_A;

    int m0 = blockIdx.y * 128;
    int n0 = blockIdx.x * 128;
    int tid = threadIdx.x;
    int lane = tid & 31, wid = tid >> 5;
    int gid = lane >> 2, tig = lane & 3;
    int warp_m = wid >> 2;                   // 0..1
    int warp_n = wid & 3;                    // 0..3

    float acc[4][4][4];
#pragma unroll
    for (int mi = 0; mi < 4; mi++)
#pragma unroll
        for (int ni = 0; ni < 4; ni++)
#pragma unroll
            for (int j = 0; j < 4; j++) acc[mi][ni][j] = 0.f;

    int xa_row  = tid & 127;                 // A tile row
    int xa_half = tid >> 7;                  // 0/1
    int wb_kr   = tid >> 5;                  // 0..7
    int wb_c4   = (tid & 31) * 4;            // 0..124

    for (int k0 = 0; k0 < K; k0 += 32) {
        // Load A tile 128x32, transpose into As[k][m] as tf32
#pragma unroll
        for (int i = 0; i < 4; i++) {
            int chunk = xa_half + 2*i;       // 0..7 (k float4-chunk)
            float4 v = *(const float4*)&Ap[(size_t)(m0+xa_row)*K + k0 + chunk*4];
            As[(chunk*4+0)*PIT + xa_row] = f2tf32(v.x);
            As[(chunk*4+1)*PIT + xa_row] = f2tf32(v.y);
            As[(chunk*4+2)*PIT + xa_row] = f2tf32(v.z);
            As[(chunk*4+3)*PIT + xa_row] = f2tf32(v.w);
        }
        // Load W tile 32x128 into Bs[k][n] as tf32
#pragma unroll
        for (int r = 0; r < 4; r++) {
            int kr = wb_kr + r*8;
            float4 v = *(const float4*)&W[(size_t)(k0+kr)*NCOLS + n0 + wb_c4];
            uint4 u;
            u.x = f2tf32(v.x); u.y = f2tf32(v.y);
            u.z = f2tf32(v.z); u.w = f2tf32(v.w);
            *(uint4*)&Bs[kr*PIT + wb_c4] = u;
        }
        __syncthreads();

#pragma unroll
        for (int ks = 0; ks < 4; ks++) {
            int kk = ks * 8;
            uint32_t a[4][4], b[4][2];
#pragma unroll
            for (int mi = 0; mi < 4; mi++) {
                int mr = warp_m*64 + mi*16 + gid;
                a[mi][0] = As[(kk+tig  )*PIT + mr    ];
                a[mi][1] = As[(kk+tig  )*PIT + mr + 8];
                a[mi][2] = As[(kk+tig+4)*PIT + mr    ];
                a[mi][3] = As[(kk+tig+4)*PIT + mr + 8];
            }
#pragma unroll
            for (int ni = 0; ni < 4; ni++) {
                int nc = warp_n*32 + ni*8 + gid;
                b[ni][0] = Bs[(kk+tig  )*PIT + nc];
                b[ni][1] = Bs[(kk+tig+4)*PIT + nc];
            }
#pragma unroll
            for (int mi = 0; mi < 4; mi++)
#pragma unroll
                for (int ni = 0; ni < 4; ni++)
                    mma_tf32(acc[mi][ni], a[mi], b[ni]);
        }
        __syncthreads();
    }

    // Epilogue
#pragma unroll
    for (int mi = 0; mi < 4; mi++) {
        int m = m0 + warp_m*64 + mi*16 + gid;
#pragma unroll
        for (int ni = 0; ni < 4; ni++) {
            int n = n0 + warp_n*32 + ni*8 + tig*2;
            float* c = acc[mi][ni];
            float bn0 = bias[n], bn1 = bias[n+1];
            if (MODE == 1) {
                qkv_store(m,   n,   c[0] + bn0);
                qkv_store(m,   n+1, c[1] + bn1);
                qkv_store(m+8, n,   c[2] + bn0);
                qkv_store(m+8, n+1, c[3] + bn1);
            } else {
                out[(size_t)m*NCOLS + n]       = c[0] + bn0;
                out[(size_t)m*NCOLS + n+1]     = c[1] + bn1;
                out[(size_t)(m+8)*NCOLS + n]   = c[2] + bn0;
                out[(size_t)(m+8)*NCOLS + n+1] = c[3] + bn1;
            }
        }
    }
}

// ---------------------------------------------------------------------------
// Kernel 2: causal flash attention on tf32 tensor cores.
// grid = (T/128, B*H); 256 threads (8 warps); warp w owns q-rows [w*16, w*16+16).
// K and V tiles (64 keys x 64 dh) both row-major in smem, pitch 76.
// S-phase fragment loads (bank = 12*gid+tig mod 32) are conflict-free;
// PV-phase (12*tig+gid) has a 2-way conflict on 4 banks (~1-2% cost, accepted).
// ---------------------------------------------------------------------------
#define AP 76
__global__ __launch_bounds__(256) void attn_tc() {
    __shared__ uint32_t Ks[64*AP];   // [key][d], tf32 bits
    __shared__ uint32_t Vs[64*AP];   // [key][d], tf32 bits

    int tid = threadIdx.x;
    int lane = tid & 31, w = tid >> 5;
    int gid = lane >> 2, tig = lane & 3;

    int qt = gridDim.x - 1 - blockIdx.x;     // heavy tiles first
    int bh = blockIdx.y;
    int q0 = qt * 128;

    const float* Qp = g_Q + (size_t)bh * (TT*DH);
    const float* Kp = g_K + (size_t)bh * (TT*DH);
    const float* Vp = g_V + (size_t)bh * (TT*DH);

    int r0g = q0 + w*16 + gid;               // this thread's first q row
    // Q fragments, pre-scaled by 1/sqrt(dh)=0.125 (exact power of 2)
    uint32_t qf[8][4];
#pragma unroll
    for (int kk = 0; kk < 8; kk++) {
        qf[kk][0] = f2tf32(0.125f * Qp[(size_t)r0g    *DH + kk*8 + tig    ]);
        qf[kk][1] = f2tf32(0.125f * Qp[(size_t)(r0g+8)*DH + kk*8 + tig    ]);
        qf[kk][2] = f2tf32(0.125f * Qp[(size_t)r0g    *DH + kk*8 + tig + 4]);
        qf[kk][3] = f2tf32(0.125f * Qp[(size_t)(r0g+8)*DH + kk*8 + tig + 4]);
    }

    float o[8][4];
#pragma unroll
    for (int dn = 0; dn < 8; dn++)
#pragma unroll
        for (int j = 0; j < 4; j++) o[dn][j] = 0.f;
    float m0r = -1e30f, m1r = -1e30f, l0 = 0.f, l1 = 0.f;

    int ntiles = 2*qt + 2;
    for (int jt = 0; jt < ntiles; jt++) {
        int k0g = jt * 64;
        __syncthreads();                      // smem reuse guard
        // Load K,V tiles (64x64) row-major, tf32
#pragma unroll
        for (int i = 0; i < 4; i++) {
            int idx = tid + i*256;            // 0..1023
            int r = idx >> 4;
            int c4 = (idx & 15) * 4;
            float4 kv = *(const float4*)&Kp[(size_t)(k0g+r)*DH + c4];
            uint4 ku; ku.x = f2tf32(kv.x); ku.y = f2tf32(kv.y);
            ku.z = f2tf32(kv.z); ku.w = f2tf32(kv.w);
            *(uint4*)&Ks[r*AP + c4] = ku;
            float4 vv = *(const float4*)&Vp[(size_t)(k0g+r)*DH + c4];
            uint4 vu; vu.x = f2tf32(vv.x); vu.y = f2tf32(vv.y);
            vu.z = f2tf32(vv.z); vu.w = f2tf32(vv.w);
            *(uint4*)&Vs[r*AP + c4] = vu;
        }
        __syncthreads();

        if (k0g > q0 + w*16 + 15) continue;   // whole warp masked (barriers match)

        // ---- S = Q K^T : 16x64 per warp ----
        float c[8][4];
#pragma unroll
        for (int nf = 0; nf < 8; nf++)
#pragma unroll
            for (int j = 0; j < 4; j++) c[nf][j] = 0.f;
#pragma unroll
        for (int kk = 0; kk < 8; kk++) {
#pragma unroll
            for (int nf = 0; nf < 8; nf++) {
                uint32_t b[2];
                b[0] = Ks[(nf*8+gid)*AP + kk*8 + tig    ];
                b[1] = Ks[(nf*8+gid)*AP + kk*8 + tig + 4];
                mma_tf32(c[nf], qf[kk], b);
            }
        }

        // ---- causal mask (only top two tiles intersect diagonal) ----
        if (jt >= 2*qt) {
#pragma unroll
            for (int nf = 0; nf < 8; nf++) {
#pragma unroll
                for (int j = 0; j < 2; j++) {
                    int col = k0g + nf*8 + 2*tig + j;
                    if (col > r0g)     c[nf][j]   = -1e30f;
                    if (col > r0g + 8) c[nf][2+j] = -1e30f;
                }
            }
        }

        // ---- online softmax (rows gid and gid+8) ----
        float mx0 = -1e30f, mx1 = -1e30f;
#pragma unroll
        for (int nf = 0; nf < 8; nf++) {
            mx0 = fmaxf(mx0, fmaxf(c[nf][0], c[nf][1]));
            mx1 = fmaxf(mx1, fmaxf(c[nf][2], c[nf][3]));
        }
        mx0 = fmaxf(mx0, __shfl_xor_sync(0xffffffffu, mx0, 1));
        mx0 = fmaxf(mx0, __shfl_xor_sync(0xffffffffu, mx0, 2));
        mx1 = fmaxf(mx1, __shfl_xor_sync(0xffffffffu, mx1, 1));
        mx1 = fmaxf(mx1, __shfl_xor_sync(0xffffffffu, mx1, 2));
        float mn0 = fmaxf(m0r, mx0), mn1 = fmaxf(m1r, mx1);
        float cor0 = __expf(m0r - mn0), cor1 = __expf(m1r - mn1);
        m0r = mn0; m1r = mn1;
        float rs0 = 0.f, rs1 = 0.f;
#pragma unroll
        for (int nf = 0; nf < 8; nf++) {
            c[nf][0] = __expf(c[nf][0] - mn0); rs0 += c[nf][0];
            c[nf][1] = __expf(c[nf][1] - mn0); rs0 += c[nf][1];
            c[nf][2] = __expf(c[nf][2] - mn1); rs1 += c[nf][2];
            c[nf][3] = __expf(c[nf][3] - mn1); rs1 += c[nf][3];
        }
        rs0 += __shfl_xor_sync(0xffffffffu, rs0, 1);
        rs0 += __shfl_xor_sync(0xffffffffu, rs0, 2);
        rs1 += __shfl_xor_sync(0xffffffffu, rs1, 1);
        rs1 += __shfl_xor_sync(0xffffffffu, rs1, 2);
        l0 = l0*cor0 + rs0;
        l1 = l1*cor1 + rs1;
#pragma unroll
        for (int dn = 0; dn < 8; dn++) {
            o[dn][0] *= cor0; o[dn][1] *= cor0;
            o[dn][2] *= cor1; o[dn][3] *= cor1;
        }

        // convert P to tf32 bits in place (shuffle bit patterns as floats)
#pragma unroll
        for (int nf = 0; nf < 8; nf++)
#pragma unroll
            for (int j = 0; j < 4; j++)
                c[nf][j] = __uint_as_float(f2tf32(c[nf][j]));

        // ---- O += P V : convert C-frag -> A-frag via shuffles ----
        int src0 = (lane & ~3) | (tig >> 1);       // owner of col tig
        int src1 = src0 + 2;                        // owner of col tig+4
        bool odd = (tig & 1);
#pragma unroll
        for (int kk = 0; kk < 8; kk++) {
            float f0 = __shfl_sync(0xffffffffu, c[kk][0], src0);
            float f1 = __shfl_sync(0xffffffffu, c[kk][1], src0);
            float f2 = __shfl_sync(0xffffffffu, c[kk][2], src0);
            float f3 = __shfl_sync(0xffffffffu, c[kk][3], src0);
            float h0 = __shfl_sync(0xffffffffu, c[kk][0], src1);
            float h1 = __shfl_sync(0xffffffffu, c[kk][1], src1);
            float h2 = __shfl_sync(0xffffffffu, c[kk][2], src1);
            float h3 = __shfl_sync(0xffffffffu, c[kk][3], src1);
            uint32_t a[4];
            a[0] = __float_as_uint(odd ? f1 : f0);  // (row gid,   col kk*8+tig)
            a[1] = __float_as_uint(odd ? f3 : f2);  // (row gid+8, col kk*8+tig)
            a[2] = __float_as_uint(odd ? h1 : h0);  // (row gid,   col kk*8+tig+4)
            a[3] = __float_as_uint(odd ? h3 : h2);  // (row gid+8, col kk*8+tig+4)
#pragma unroll
            for (int dn = 0; dn < 8; dn++) {
                uint32_t b[2];
                b[0] = Vs[(kk*8+tig  )*AP + dn*8 + gid];
                b[1] = Vs[(kk*8+tig+4)*AP + dn*8 + gid];
                mma_tf32(o[dn], a, b);
            }
        }
    }

    // ---- epilogue: write [B,T,H,dh] (== merged [B,T,D]) ----
    float inv0 = 1.0f / l0, inv1 = 1.0f / l1;
    int bb = bh >> 4, h = bh & 15;
#pragma unroll
    for (int dn = 0; dn < 8; dn++) {
        int dd = dn*8 + 2*tig;
        size_t base0 = ((size_t)(bb*TT + r0g    )*HH + h)*DH + dd;
        size_t base1 = ((size_t)(bb*TT + r0g + 8)*HH + h)*DH + dd;
        g_A[base0]     = o[dn][0] * inv0;
        g_A[base0 + 1] = o[dn][1] * inv0;
        g_A[base1]     = o[dn][2] * inv1;
        g_A[base1 + 1] = o[dn][3] * inv1;
    }
}

// ---------------------------------------------------------------------------
extern "C" void kernel_launch(void* const* d_in, const int* in_sizes, int n_in,
                              void* d_out, int out_size) {
    const float* x      = (const float*)d_in[0];
    const float* W_attn = (const float*)d_in[1];
    const float* b_attn = (const float*)d_in[2];
    const float* W_proj = (const float*)d_in[3];
    const float* b_proj = (const float*)d_in[4];
    float* out = (float*)d_out;

    // QKV projection (tf32 tensor cores): grid (3072/128=24, 4096/128=32)
    gemm_tf32<3*DD, 1><<<dim3(24, 32), 256>>>(x, W_attn, b_attn, nullptr);

    // Flash attention (tf32 tensor cores): grid (2048/128=16, 32)
    attn_tc<<<dim3(TT/128, BB*HH), 256>>>();

    // Output projection (tf32 tensor cores): grid (1024/128=8, 32)
    gemm_tf32<DD, 0><<<dim3(8, 32), 256>>>(nullptr, W_proj, b_proj, out);
}

// round 12
// speedup vs baseline: 3.0308x; 1.1367x over previous
#include <cuda_runtime.h>
#include <cuda_bf16.h>
#include <cstdint>

// Problem constants
#define BB 2
#define TT 2048
#define DD 1024
#define HH 16
#define DH 64
#define MROWS (BB*TT)      // 4096

// Scratch (device globals — no allocation allowed)
__device__ float g_Q[(size_t)BB*HH*TT*DH];   // [B,H,T,dh]
__device__ float g_K[(size_t)BB*HH*TT*DH];
__device__ float g_V[(size_t)BB*HH*TT*DH];
__device__ float g_A[(size_t)MROWS*DD];      // [B,T,D] attention output

// ---------------------------------------------------------------------------
// tf32 / cp.async helpers
// ---------------------------------------------------------------------------
__device__ __forceinline__ uint32_t f2tf32(float f) {
    uint32_t r;
    asm("cvt.rna.tf32.f32 %0, %1;" : "=r"(r) : "f"(f));
    return r;
}

__device__ __forceinline__ void mma_tf32(float* c, const uint32_t* a, const uint32_t* b) {
    asm volatile(
        "mma.sync.aligned.m16n8k8.row.col.f32.tf32.tf32.f32 "
        "{%0,%1,%2,%3}, {%4,%5,%6,%7}, {%8,%9}, {%0,%1,%2,%3};"
        : "+f"(c[0]), "+f"(c[1]), "+f"(c[2]), "+f"(c[3])
        : "r"(a[0]), "r"(a[1]), "r"(a[2]), "r"(a[3]),
          "r"(b[0]), "r"(b[1]));
}

__device__ __forceinline__ void cp16(void* smem_dst, const void* gsrc) {
    uint32_t d = (uint32_t)__cvta_generic_to_shared(smem_dst);
    asm volatile("cp.async.cg.shared.global [%0], [%1], 16;" :: "r"(d), "l"(gsrc));
}
#define CP_COMMIT() asm volatile("cp.async.commit_group;")
#define CP_WAIT0()  asm volatile("cp.async.wait_group 0;")

__device__ __forceinline__ void qkv_store(int m, int n, float v) {
    int bb = m >> 11, t = m & 2047;
    int sel = n >> 10;            // 0=q,1=k,2=v
    int r   = n & 1023;
    int h   = r >> 6;
    int dd  = r & 63;
    float* dst = (sel == 0) ? g_Q : (sel == 1 ? g_K : g_V);
    dst[((size_t)(bb*HH + h)*TT + t)*DH + dd] = v;
}

// ---------------------------------------------------------------------------
// tf32 tensor-core GEMM with cp.async 2-stage pipeline.
// C[4096, NCOLS] = A[4096,1024] @ W[1024,NCOLS] + bias
// 128x128x32 CTA tile, 256 threads (8 warps 2x4), warp tile 64x32.
//   A [128][PA=36]  -> frag bank = 4*gid+tig (bijective, conflict-free)
//   B [32][PB=132]  -> frag bank = 4*tig+gid (bijective, conflict-free)
// RNA tf32 conversion applied at fragment-load time.
// ---------------------------------------------------------------------------
#define PA 36
#define PB 132
#define ASZ (128*PA)
#define BSZ (32*PB)
#define GEMM_SMEM ((2*ASZ + 2*BSZ)*4)

template<int NCOLS, int MODE>
__device__ __forceinline__ void gemm_prefetch(float* Ad, float* Bd,
                                              const float* __restrict__ Ap,
                                              const float* __restrict__ W,
                                              int m0, int n0, int k0, int tid) {
#pragma unroll
    for (int j = 0; j < 4; j++) {
        int id = tid + j*256;               // 0..1023
        int row = id >> 3, c = id & 7;      // A: 128 rows x 8 chunks
        cp16(Ad + row*PA + c*4, &Ap[(size_t)(m0+row)*DD + k0 + c*4]);
    }
#pragma unroll
    for (int j = 0; j < 4; j++) {
        int id = tid + j*256;
        int kr = id >> 5, c = id & 31;      // B: 32 rows x 32 chunks
        cp16(Bd + kr*PB + c*4, &W[(size_t)(k0+kr)*NCOLS + n0 + c*4]);
    }
}

template<int NCOLS, int MODE>
__global__ __launch_bounds__(256) void gemm_tf32(const float* __restrict__ Ain,
                                                 const float* __restrict__ W,
                                                 const float* __restrict__ bias,
                                                 float* __restrict__ out) {
    extern __shared__ float sm[];
    float* As = sm;                 // 2 stages of ASZ
    float* Bs = sm + 2*ASZ;         // 2 stages of BSZ

    const float* Ap = (MODE == 1) ? Ain : g_A;

    int m0 = blockIdx.y * 128;
    int n0 = blockIdx.x * 128;
    int tid = threadIdx.x;
    int lane = tid & 31, wid = tid >> 5;
    int gid = lane >> 2, tig = lane & 3;
    int warp_m = wid >> 2;                   // 0..1
    int warp_n = wid & 3;                    // 0..3

    float acc[4][4][4];
#pragma unroll
    for (int mi = 0; mi < 4; mi++)
#pragma unroll
        for (int ni = 0; ni < 4; ni++)
#pragma unroll
            for (int j = 0; j < 4; j++) acc[mi][ni][j] = 0.f;

    const int NKC = DD / 32;                 // 32 k-chunks
    gemm_prefetch<NCOLS, MODE>(As, Bs, Ap, W, m0, n0, 0, tid);
    CP_COMMIT();

    for (int i = 0; i < NKC; i++) {
        CP_WAIT0();                          // my stage-i groups done
        __syncthreads();                     // stage i visible, stage i-1 reads done
        if (i + 1 < NKC)
            gemm_prefetch<NCOLS, MODE>(As + ((i+1)&1)*ASZ, Bs + ((i+1)&1)*BSZ,
                                       Ap, W, m0, n0, (i+1)*32, tid);
        CP_COMMIT();                         // always commit (group accounting)

        const float* Ab = As + (i&1)*ASZ;
        const float* Bb = Bs + (i&1)*BSZ;
#pragma unroll
        for (int ks = 0; ks < 4; ks++) {
            int kk = ks * 8;
            uint32_t a[4][4], b[4][2];
#pragma unroll
            for (int mi = 0; mi < 4; mi++) {
                int mr = warp_m*64 + mi*16 + gid;
                a[mi][0] = f2tf32(Ab[mr    *PA + kk + tig    ]);
                a[mi][1] = f2tf32(Ab[(mr+8)*PA + kk + tig    ]);
                a[mi][2] = f2tf32(Ab[mr    *PA + kk + tig + 4]);
                a[mi][3] = f2tf32(Ab[(mr+8)*PA + kk + tig + 4]);
            }
#pragma unroll
            for (int ni = 0; ni < 4; ni++) {
                int nc = warp_n*32 + ni*8 + gid;
                b[ni][0] = f2tf32(Bb[(kk+tig  )*PB + nc]);
                b[ni][1] = f2tf32(Bb[(kk+tig+4)*PB + nc]);
            }
#pragma unroll
            for (int mi = 0; mi < 4; mi++)
#pragma unroll
                for (int ni = 0; ni < 4; ni++)
                    mma_tf32(acc[mi][ni], a[mi], b[ni]);
        }
    }

    // Epilogue
#pragma unroll
    for (int mi = 0; mi < 4; mi++) {
        int m = m0 + warp_m*64 + mi*16 + gid;
#pragma unroll
        for (int ni = 0; ni < 4; ni++) {
            int n = n0 + warp_n*32 + ni*8 + tig*2;
            float* c = acc[mi][ni];
            float bn0 = bias[n], bn1 = bias[n+1];
            if (MODE == 1) {
                qkv_store(m,   n,   c[0] + bn0);
                qkv_store(m,   n+1, c[1] + bn1);
                qkv_store(m+8, n,   c[2] + bn0);
                qkv_store(m+8, n+1, c[3] + bn1);
            } else {
                out[(size_t)m*NCOLS + n]       = c[0] + bn0;
                out[(size_t)m*NCOLS + n+1]     = c[1] + bn1;
                out[(size_t)(m+8)*NCOLS + n]   = c[2] + bn0;
                out[(size_t)(m+8)*NCOLS + n+1] = c[3] + bn1;
            }
        }
    }
}

// ---------------------------------------------------------------------------
// Kernel 2: causal flash attention, tf32 tensor cores + cp.async pipeline.
// grid = (T/128, B*H); 256 threads (8 warps); warp w owns q-rows [w*16, w*16+16).
// K/V tiles (64 keys x 64 dh) staged RAW fp32, 2-stage ping-pong, pitch 76.
// f2tf32 applied at fragment-load time.
// ---------------------------------------------------------------------------
#define AP 76
#define TSZ (64*AP)
#define ATTN_SMEM (4*TSZ*4)     // 2 stages x (K + V) tiles, fp32

__device__ __forceinline__ void attn_prefetch(float* Kd, float* Vd,
                                              const float* __restrict__ Kp,
                                              const float* __restrict__ Vp,
                                              int k0g, int tid) {
#pragma unroll
    for (int i = 0; i < 4; i++) {
        int idx = tid + i*256;              // 0..1023
        int r = idx >> 4;
        int c4 = (idx & 15) * 4;
        cp16(Kd + r*AP + c4, &Kp[(size_t)(k0g+r)*DH + c4]);
        cp16(Vd + r*AP + c4, &Vp[(size_t)(k0g+r)*DH + c4]);
    }
}

__global__ __launch_bounds__(256) void attn_tc() {
    extern __shared__ float asm_[];
    float* Ks = asm_;               // 2 stages of TSZ
    float* Vs = asm_ + 2*TSZ;       // 2 stages of TSZ

    int tid = threadIdx.x;
    int lane = tid & 31, w = tid >> 5;
    int gid = lane >> 2, tig = lane & 3;

    int qt = gridDim.x - 1 - blockIdx.x;     // heavy tiles first
    int bh = blockIdx.y;
    int q0 = qt * 128;

    const float* Qp = g_Q + (size_t)bh * (TT*DH);
    const float* Kp = g_K + (size_t)bh * (TT*DH);
    const float* Vp = g_V + (size_t)bh * (TT*DH);

    int r0g = q0 + w*16 + gid;               // this thread's first q row
    // Q fragments, pre-scaled by 1/sqrt(dh)=0.125 (exact power of 2)
    uint32_t qf[8][4];
#pragma unroll
    for (int kk = 0; kk < 8; kk++) {
        qf[kk][0] = f2tf32(0.125f * Qp[(size_t)r0g    *DH + kk*8 + tig    ]);
        qf[kk][1] = f2tf32(0.125f * Qp[(size_t)(r0g+8)*DH + kk*8 + tig    ]);
        qf[kk][2] = f2tf32(0.125f * Qp[(size_t)r0g    *DH + kk*8 + tig + 4]);
        qf[kk][3] = f2tf32(0.125f * Qp[(size_t)(r0g+8)*DH + kk*8 + tig + 4]);
    }

    float o[8][4];
#pragma unroll
    for (int dn = 0; dn < 8; dn++)
#pragma unroll
        for (int j = 0; j < 4; j++) o[dn][j] = 0.f;
    float m0r = -1e30f, m1r = -1e30f, l0 = 0.f, l1 = 0.f;

    int ntiles = 2*qt + 2;
    attn_prefetch(Ks, Vs, Kp, Vp, 0, tid);
    CP_COMMIT();

    for (int jt = 0; jt < ntiles; jt++) {
        int k0g = jt * 64;
        CP_WAIT0();                           // tile jt staged (my copies)
        __syncthreads();                      // all copies visible; prev reads done
        if (jt + 1 < ntiles)
            attn_prefetch(Ks + ((jt+1)&1)*TSZ, Vs + ((jt+1)&1)*TSZ,
                          Kp, Vp, (jt+1)*64, tid);
        CP_COMMIT();                          // uniform group accounting

        if (k0g > q0 + w*16 + 15) continue;   // whole warp masked (barriers above)

        const float* Kb = Ks + (jt&1)*TSZ;
        const float* Vb = Vs + (jt&1)*TSZ;

        // ---- S = Q K^T : 16x64 per warp ----
        float c[8][4];
#pragma unroll
        for (int nf = 0; nf < 8; nf++)
#pragma unroll
            for (int j = 0; j < 4; j++) c[nf][j] = 0.f;
#pragma unroll
        for (int kk = 0; kk < 8; kk++) {
#pragma unroll
            for (int nf = 0; nf < 8; nf++) {
                uint32_t b[2];
                b[0] = f2tf32(Kb[(nf*8+gid)*AP + kk*8 + tig    ]);
                b[1] = f2tf32(Kb[(nf*8+gid)*AP + kk*8 + tig + 4]);
                mma_tf32(c[nf], qf[kk], b);
            }
        }

        // ---- causal mask (only top two tiles intersect diagonal) ----
        if (jt >= 2*qt) {
#pragma unroll
            for (int nf = 0; nf < 8; nf++) {
#pragma unroll
                for (int j = 0; j < 2; j++) {
                    int col = k0g + nf*8 + 2*tig + j;
                    if (col > r0g)     c[nf][j]   = -1e30f;
                    if (col > r0g + 8) c[nf][2+j] = -1e30f;
                }
            }
        }

        // ---- online softmax (rows gid and gid+8) ----
        float mx0 = -1e30f, mx1 = -1e30f;
#pragma unroll
        for (int nf = 0; nf < 8; nf++) {
            mx0 = fmaxf(mx0, fmaxf(c[nf][0], c[nf][1]));
            mx1 = fmaxf(mx1, fmaxf(c[nf][2], c[nf][3]));
        }
        mx0 = fmaxf(mx0, __shfl_xor_sync(0xffffffffu, mx0, 1));
        mx0 = fmaxf(mx0, __shfl_xor_sync(0xffffffffu, mx0, 2));
        mx1 = fmaxf(mx1, __shfl_xor_sync(0xffffffffu, mx1, 1));
        mx1 = fmaxf(mx1, __shfl_xor_sync(0xffffffffu, mx1, 2));
        float mn0 = fmaxf(m0r, mx0), mn1 = fmaxf(m1r, mx1);
        float cor0 = __expf(m0r - mn0), cor1 = __expf(m1r - mn1);
        m0r = mn0; m1r = mn1;
        float rs0 = 0.f, rs1 = 0.f;
#pragma unroll
        for (int nf = 0; nf < 8; nf++) {
            c[nf][0] = __expf(c[nf][0] - mn0); rs0 += c[nf][0];
            c[nf][1] = __expf(c[nf][1] - mn0); rs0 += c[nf][1];
            c[nf][2] = __expf(c[nf][2] - mn1); rs1 += c[nf][2];
            c[nf][3] = __expf(c[nf][3] - mn1); rs1 += c[nf][3];
        }
        rs0 += __shfl_xor_sync(0xffffffffu, rs0, 1);
        rs0 += __shfl_xor_sync(0xffffffffu, rs0, 2);
        rs1 += __shfl_xor_sync(0xffffffffu, rs1, 1);
        rs1 += __shfl_xor_sync(0xffffffffu, rs1, 2);
        l0 = l0*cor0 + rs0;
        l1 = l1*cor1 + rs1;
#pragma unroll
        for (int dn = 0; dn < 8; dn++) {
            o[dn][0] *= cor0; o[dn][1] *= cor0;
            o[dn][2] *= cor1; o[dn][3] *= cor1;
        }

        // convert P to tf32 bits in place
#pragma unroll
        for (int nf = 0; nf < 8; nf++)
#pragma unroll
            for (int j = 0; j < 4; j++)
                c[nf][j] = __uint_as_float(f2tf32(c[nf][j]));

        // ---- O += P V : convert C-frag -> A-frag via shuffles ----
        int src0 = (lane & ~3) | (tig >> 1);
        int src1 = src0 + 2;
        bool odd = (tig & 1);
#pragma unroll
        for (int kk = 0; kk < 8; kk++) {
            float f0 = __shfl_sync(0xffffffffu, c[kk][0], src0);
            float f1 = __shfl_sync(0xffffffffu, c[kk][1], src0);
            float f2 = __shfl_sync(0xffffffffu, c[kk][2], src0);
            float f3 = __shfl_sync(0xffffffffu, c[kk][3], src0);
            float h0 = __shfl_sync(0xffffffffu, c[kk][0], src1);
            float h1 = __shfl_sync(0xffffffffu, c[kk][1], src1);
            float h2 = __shfl_sync(0xffffffffu, c[kk][2], src1);
            float h3 = __shfl_sync(0xffffffffu, c[kk][3], src1);
            uint32_t a[4];
            a[0] = __float_as_uint(odd ? f1 : f0);  // (row gid,   col kk*8+tig)
            a[1] = __float_as_uint(odd ? f3 : f2);  // (row gid+8, col kk*8+tig)
            a[2] = __float_as_uint(odd ? h1 : h0);  // (row gid,   col kk*8+tig+4)
            a[3] = __float_as_uint(odd ? h3 : h2);  // (row gid+8, col kk*8+tig+4)
#pragma unroll
            for (int dn = 0; dn < 8; dn++) {
                uint32_t b[2];
                b[0] = f2tf32(Vb[(kk*8+tig  )*AP + dn*8 + gid]);
                b[1] = f2tf32(Vb[(kk*8+tig+4)*AP + dn*8 + gid]);
                mma_tf32(o[dn], a, b);
            }
        }
    }

    // ---- epilogue: write [B,T,H,dh] (== merged [B,T,D]) ----
    float inv0 = 1.0f / l0, inv1 = 1.0f / l1;
    int bb = bh >> 4, h = bh & 15;
#pragma unroll
    for (int dn = 0; dn < 8; dn++) {
        int dd = dn*8 + 2*tig;
        size_t base0 = ((size_t)(bb*TT + r0g    )*HH + h)*DH + dd;
        size_t base1 = ((size_t)(bb*TT + r0g + 8)*HH + h)*DH + dd;
        g_A[base0]     = o[dn][0] * inv0;
        g_A[base0 + 1] = o[dn][1] * inv0;
        g_A[base1]     = o[dn][2] * inv1;
        g_A[base1 + 1] = o[dn][3] * inv1;
    }
}

// ---------------------------------------------------------------------------
extern "C" void kernel_launch(void* const* d_in, const int* in_sizes, int n_in,
                              void* d_out, int out_size) {
    const float* x      = (const float*)d_in[0];
    const float* W_attn = (const float*)d_in[1];
    const float* b_attn = (const float*)d_in[2];
    const float* W_proj = (const float*)d_in[3];
    const float* b_proj = (const float*)d_in[4];
    float* out = (float*)d_out;

    cudaFuncSetAttribute(gemm_tf32<3*DD, 1>,
                         cudaFuncAttributeMaxDynamicSharedMemorySize, GEMM_SMEM);
    cudaFuncSetAttribute(gemm_tf32<DD, 0>,
                         cudaFuncAttributeMaxDynamicSharedMemorySize, GEMM_SMEM);
    cudaFuncSetAttribute(attn_tc,
                         cudaFuncAttributeMaxDynamicSharedMemorySize, ATTN_SMEM);

    // QKV projection: grid (3072/128=24, 4096/128=32)
    gemm_tf32<3*DD, 1><<<dim3(24, 32), 256, GEMM_SMEM>>>(x, W_attn, b_attn, nullptr);

    // Flash attention: grid (2048/128=16, 32)
    attn_tc<<<dim3(TT/128, BB*HH), 256, ATTN_SMEM>>>();

    // Output projection: grid (1024/128=8, 32)
    gemm_tf32<DD, 0><<<dim3(8, 32), 256, GEMM_SMEM>>>(nullptr, W_proj, b_proj, out);
}

// round 17
// speedup vs baseline: 3.4612x; 1.1420x over previous
#include <cuda_runtime.h>
#include <cuda_bf16.h>
#include <cstdint>

// Problem constants
#define BB 2
#define TT 2048
#define DD 1024
#define HH 16
#define DH 64
#define MROWS (BB*TT)      // 4096

// Scratch (device globals — no allocation allowed).
// g_Q/g_K/g_V/g_A/g_Xc/g_Wq/g_Wp hold tf32 BIT PATTERNS stored as float.
__device__ float g_Q[(size_t)BB*HH*TT*DH];   // [B,H,T,dh], pre-scaled 0.125, tf32 bits
__device__ float g_K[(size_t)BB*HH*TT*DH];   // tf32 bits
__device__ float g_V[(size_t)BB*HH*TT*DH];   // tf32 bits
__device__ float g_A[(size_t)MROWS*DD];      // [B,T,D] attention out, tf32 bits
__device__ float g_Xc[(size_t)MROWS*DD];     // x converted to tf32 bits
__device__ float g_Wq[(size_t)DD*3*DD];      // W_attn tf32 bits
__device__ float g_Wp[(size_t)DD*DD];        // W_proj tf32 bits

// ---------------------------------------------------------------------------
// tf32 / cp.async helpers
// ---------------------------------------------------------------------------
__device__ __forceinline__ uint32_t f2tf32(float f) {
    uint32_t r;
    asm("cvt.rna.tf32.f32 %0, %1;" : "=r"(r) : "f"(f));
    return r;
}

__device__ __forceinline__ void mma_tf32(float* c, const uint32_t* a, const uint32_t* b) {
    asm volatile(
        "mma.sync.aligned.m16n8k8.row.col.f32.tf32.tf32.f32 "
        "{%0,%1,%2,%3}, {%4,%5,%6,%7}, {%8,%9}, {%0,%1,%2,%3};"
        : "+f"(c[0]), "+f"(c[1]), "+f"(c[2]), "+f"(c[3])
        : "r"(a[0]), "r"(a[1]), "r"(a[2]), "r"(a[3]),
          "r"(b[0]), "r"(b[1]));
}

__device__ __forceinline__ void cp16(void* smem_dst, const void* gsrc) {
    uint32_t d = (uint32_t)__cvta_generic_to_shared(smem_dst);
    asm volatile("cp.async.cg.shared.global [%0], [%1], 16;" :: "r"(d), "l"(gsrc));
}
#define CP_COMMIT() asm volatile("cp.async.commit_group;")
#define CP_WAIT0()  asm volatile("cp.async.wait_group 0;")

// ---------------------------------------------------------------------------
// Prep: convert fp32 arrays to tf32 bit patterns (once, outside hot loops).
// SEL: 0 = x -> g_Xc, 1 = W_attn -> g_Wq, 2 = W_proj -> g_Wp.
// ---------------------------------------------------------------------------
template<int SEL>
__global__ __launch_bounds__(256) void conv_tf32(const float* __restrict__ src, int n) {
    float* dst = (SEL == 0) ? g_Xc : (SEL == 1 ? g_Wq : g_Wp);
    int i = (blockIdx.x * 256 + threadIdx.x) * 4;
    if (i < n) {
        float4 v = *(const float4*)&src[i];
        uint4 u;
        u.x = f2tf32(v.x); u.y = f2tf32(v.y);
        u.z = f2tf32(v.z); u.w = f2tf32(v.w);
        *(uint4*)&dst[i] = u;
    }
}

// QKV epilogue store: convert once here (Q pre-scaled by 1/sqrt(dh)=0.125).
__device__ __forceinline__ void qkv_store(int m, int n, float v) {
    int bb = m >> 11, t = m & 2047;
    int sel = n >> 10;            // 0=q,1=k,2=v
    int r   = n & 1023;
    int h   = r >> 6;
    int dd  = r & 63;
    float* dst = (sel == 0) ? g_Q : (sel == 1 ? g_K : g_V);
    float sv = (sel == 0) ? 0.125f * v : v;
    dst[((size_t)(bb*HH + h)*TT + t)*DH + dd] = __uint_as_float(f2tf32(sv));
}

// ---------------------------------------------------------------------------
// tf32 tensor-core GEMM, cp.async 2-stage pipeline, pre-converted operands.
// C[4096, NCOLS] = A[4096,1024] @ W[1024,NCOLS] + bias
// MODE 1: A=g_Xc, W=g_Wq, scatter epilogue (tf32 bits) into g_Q/g_K/g_V.
// MODE 0: A=g_A (tf32 bits), W=g_Wp, fp32 epilogue into out.
// 128x128x32 CTA tile, 256 threads (8 warps 2x4), warp tile 64x32.
//   A [128][PA=36]  -> frag bank = 4*gid+tig (bijective, conflict-free)
//   B [32][PB=132]  -> frag bank = 4*tig+gid (bijective, conflict-free)
// Fragment loads are pure LDS bit-casts (no CVT in mainloop).
// ---------------------------------------------------------------------------
#define PA 36
#define PB 132
#define ASZ (128*PA)
#define BSZ (32*PB)
#define GEMM_SMEM ((2*ASZ + 2*BSZ)*4)

template<int NCOLS>
__device__ __forceinline__ void gemm_prefetch(float* Ad, float* Bd,
                                              const float* __restrict__ Ap,
                                              const float* __restrict__ W,
                                              int m0, int n0, int k0, int tid) {
#pragma unroll
    for (int j = 0; j < 4; j++) {
        int id = tid + j*256;               // 0..1023
        int row = id >> 3, c = id & 7;      // A: 128 rows x 8 chunks
        cp16(Ad + row*PA + c*4, &Ap[(size_t)(m0+row)*DD + k0 + c*4]);
    }
#pragma unroll
    for (int j = 0; j < 4; j++) {
        int id = tid + j*256;
        int kr = id >> 5, c = id & 31;      // B: 32 rows x 32 chunks
        cp16(Bd + kr*PB + c*4, &W[(size_t)(k0+kr)*NCOLS + n0 + c*4]);
    }
}

template<int NCOLS, int MODE>
__global__ __launch_bounds__(256) void gemm_tf32(const float* __restrict__ bias,
                                                 float* __restrict__ out) {
    extern __shared__ float sm[];
    float* As = sm;                 // 2 stages of ASZ
    float* Bs = sm + 2*ASZ;         // 2 stages of BSZ

    const float* Ap = (MODE == 1) ? g_Xc : g_A;
    const float* W  = (MODE == 1) ? g_Wq : g_Wp;

    int m0 = blockIdx.y * 128;
    int n0 = blockIdx.x * 128;
    int tid = threadIdx.x;
    int lane = tid & 31, wid = tid >> 5;
    int gid = lane >> 2, tig = lane & 3;
    int warp_m = wid >> 2;                   // 0..1
    int warp_n = wid & 3;                    // 0..3

    float acc[4][4][4];
#pragma unroll
    for (int mi = 0; mi < 4; mi++)
#pragma unroll
        for (int ni = 0; ni < 4; ni++)
#pragma unroll
            for (int j = 0; j < 4; j++) acc[mi][ni][j] = 0.f;

    const int NKC = DD / 32;                 // 32 k-chunks
    gemm_prefetch<NCOLS>(As, Bs, Ap, W, m0, n0, 0, tid);
    CP_COMMIT();

    for (int i = 0; i < NKC; i++) {
        CP_WAIT0();                          // my stage-i groups done
        __syncthreads();                     // stage i visible, stage i-1 reads done
        if (i + 1 < NKC)
            gemm_prefetch<NCOLS>(As + ((i+1)&1)*ASZ, Bs + ((i+1)&1)*BSZ,
                                 Ap, W, m0, n0, (i+1)*32, tid);
        CP_COMMIT();                         // always commit (group accounting)

        const float* Ab = As + (i&1)*ASZ;
        const float* Bb = Bs + (i&1)*BSZ;
#pragma unroll
        for (int ks = 0; ks < 4; ks++) {
            int kk = ks * 8;
            uint32_t a[4][4], b[4][2];
#pragma unroll
            for (int mi = 0; mi < 4; mi++) {
                int mr = warp_m*64 + mi*16 + gid;
                a[mi][0] = __float_as_uint(Ab[mr    *PA + kk + tig    ]);
                a[mi][1] = __float_as_uint(Ab[(mr+8)*PA + kk + tig    ]);
                a[mi][2] = __float_as_uint(Ab[mr    *PA + kk + tig + 4]);
                a[mi][3] = __float_as_uint(Ab[(mr+8)*PA + kk + tig + 4]);
            }
#pragma unroll
            for (int ni = 0; ni < 4; ni++) {
                int nc = warp_n*32 + ni*8 + gid;
                b[ni][0] = __float_as_uint(Bb[(kk+tig  )*PB + nc]);
                b[ni][1] = __float_as_uint(Bb[(kk+tig+4)*PB + nc]);
            }
#pragma unroll
            for (int mi = 0; mi < 4; mi++)
#pragma unroll
                for (int ni = 0; ni < 4; ni++)
                    mma_tf32(acc[mi][ni], a[mi], b[ni]);
        }
    }

    // Epilogue
#pragma unroll
    for (int mi = 0; mi < 4; mi++) {
        int m = m0 + warp_m*64 + mi*16 + gid;
#pragma unroll
        for (int ni = 0; ni < 4; ni++) {
            int n = n0 + warp_n*32 + ni*8 + tig*2;
            float* c = acc[mi][ni];
            float bn0 = bias[n], bn1 = bias[n+1];
            if (MODE == 1) {
                qkv_store(m,   n,   c[0] + bn0);
                qkv_store(m,   n+1, c[1] + bn1);
                qkv_store(m+8, n,   c[2] + bn0);
                qkv_store(m+8, n+1, c[3] + bn1);
            } else {
                out[(size_t)m*NCOLS + n]       = c[0] + bn0;
                out[(size_t)m*NCOLS + n+1]     = c[1] + bn1;
                out[(size_t)(m+8)*NCOLS + n]   = c[2] + bn0;
                out[(size_t)(m+8)*NCOLS + n+1] = c[3] + bn1;
            }
        }
    }
}

// ---------------------------------------------------------------------------
// Kernel 2: causal flash attention, tf32 tensor cores + cp.async pipeline.
// grid = (T/128, B*H); 256 threads (8 warps); warp w owns q-rows [w*16, w*16+16).
// Q/K/V in gmem already hold tf32 bits (Q pre-scaled 0.125) -> fragment loads
// are pure LDS/LDG bit-casts; only P conversion (32/tile) remains in-loop.
// K/V tiles 2-stage ping-pong, pitch 76.
// ---------------------------------------------------------------------------
#define AP 76
#define TSZ (64*AP)
#define ATTN_SMEM (4*TSZ*4)     // 2 stages x (K + V) tiles

__device__ __forceinline__ void attn_prefetch(float* Kd, float* Vd,
                                              const float* __restrict__ Kp,
                                              const float* __restrict__ Vp,
                                              int k0g, int tid) {
#pragma unroll
    for (int i = 0; i < 4; i++) {
        int idx = tid + i*256;              // 0..1023
        int r = idx >> 4;
        int c4 = (idx & 15) * 4;
        cp16(Kd + r*AP + c4, &Kp[(size_t)(k0g+r)*DH + c4]);
        cp16(Vd + r*AP + c4, &Vp[(size_t)(k0g+r)*DH + c4]);
    }
}

__global__ __launch_bounds__(256) void attn_tc() {
    extern __shared__ float asm_[];
    float* Ks = asm_;               // 2 stages of TSZ
    float* Vs = asm_ + 2*TSZ;       // 2 stages of TSZ

    int tid = threadIdx.x;
    int lane = tid & 31, w = tid >> 5;
    int gid = lane >> 2, tig = lane & 3;

    int qt = gridDim.x - 1 - blockIdx.x;     // heavy tiles first
    int bh = blockIdx.y;
    int q0 = qt * 128;

    const float* Qp = g_Q + (size_t)bh * (TT*DH);
    const float* Kp = g_K + (size_t)bh * (TT*DH);
    const float* Vp = g_V + (size_t)bh * (TT*DH);

    int r0g = q0 + w*16 + gid;               // this thread's first q row
    // Q fragments: already tf32 bits, already scaled — pure bit loads.
    uint32_t qf[8][4];
#pragma unroll
    for (int kk = 0; kk < 8; kk++) {
        qf[kk][0] = __float_as_uint(Qp[(size_t)r0g    *DH + kk*8 + tig    ]);
        qf[kk][1] = __float_as_uint(Qp[(size_t)(r0g+8)*DH + kk*8 + tig    ]);
        qf[kk][2] = __float_as_uint(Qp[(size_t)r0g    *DH + kk*8 + tig + 4]);
        qf[kk][3] = __float_as_uint(Qp[(size_t)(r0g+8)*DH + kk*8 + tig + 4]);
    }

    float o[8][4];
#pragma unroll
    for (int dn = 0; dn < 8; dn++)
#pragma unroll
        for (int j = 0; j < 4; j++) o[dn][j] = 0.f;
    float m0r = -1e30f, m1r = -1e30f, l0 = 0.f, l1 = 0.f;

    int ntiles = 2*qt + 2;
    attn_prefetch(Ks, Vs, Kp, Vp, 0, tid);
    CP_COMMIT();

    for (int jt = 0; jt < ntiles; jt++) {
        int k0g = jt * 64;
        CP_WAIT0();                           // tile jt staged (my copies)
        __syncthreads();                      // all copies visible; prev reads done
        if (jt + 1 < ntiles)
            attn_prefetch(Ks + ((jt+1)&1)*TSZ, Vs + ((jt+1)&1)*TSZ,
                          Kp, Vp, (jt+1)*64, tid);
        CP_COMMIT();                          // uniform group accounting

        if (k0g > q0 + w*16 + 15) continue;   // whole warp masked (barriers above)

        const float* Kb = Ks + (jt&1)*TSZ;
        const float* Vb = Vs + (jt&1)*TSZ;

        // ---- S = Q K^T : 16x64 per warp ----
        float c[8][4];
#pragma unroll
        for (int nf = 0; nf < 8; nf++)
#pragma unroll
            for (int j = 0; j < 4; j++) c[nf][j] = 0.f;
#pragma unroll
        for (int kk = 0; kk < 8; kk++) {
#pragma unroll
            for (int nf = 0; nf < 8; nf++) {
                uint32_t b[2];
                b[0] = __float_as_uint(Kb[(nf*8+gid)*AP + kk*8 + tig    ]);
                b[1] = __float_as_uint(Kb[(nf*8+gid)*AP + kk*8 + tig + 4]);
                mma_tf32(c[nf], qf[kk], b);
            }
        }

        // ---- causal mask (only top two tiles intersect diagonal) ----
        if (jt >= 2*qt) {
#pragma unroll
            for (int nf = 0; nf < 8; nf++) {
#pragma unroll
                for (int j = 0; j < 2; j++) {
                    int col = k0g + nf*8 + 2*tig + j;
                    if (col > r0g)     c[nf][j]   = -1e30f;
                    if (col > r0g + 8) c[nf][2+j] = -1e30f;
                }
            }
        }

        // ---- online softmax (rows gid and gid+8) ----
        float mx0 = -1e30f, mx1 = -1e30f;
#pragma unroll
        for (int nf = 0; nf < 8; nf++) {
            mx0 = fmaxf(mx0, fmaxf(c[nf][0], c[nf][1]));
            mx1 = fmaxf(mx1, fmaxf(c[nf][2], c[nf][3]));
        }
        mx0 = fmaxf(mx0, __shfl_xor_sync(0xffffffffu, mx0, 1));
        mx0 = fmaxf(mx0, __shfl_xor_sync(0xffffffffu, mx0, 2));
        mx1 = fmaxf(mx1, __shfl_xor_sync(0xffffffffu, mx1, 1));
        mx1 = fmaxf(mx1, __shfl_xor_sync(0xffffffffu, mx1, 2));
        float mn0 = fmaxf(m0r, mx0), mn1 = fmaxf(m1r, mx1);
        float cor0 = __expf(m0r - mn0), cor1 = __expf(m1r - mn1);
        m0r = mn0; m1r = mn1;
        float rs0 = 0.f, rs1 = 0.f;
#pragma unroll
        for (int nf = 0; nf < 8; nf++) {
            c[nf][0] = __expf(c[nf][0] - mn0); rs0 += c[nf][0];
            c[nf][1] = __expf(c[nf][1] - mn0); rs0 += c[nf][1];
            c[nf][2] = __expf(c[nf][2] - mn1); rs1 += c[nf][2];
            c[nf][3] = __expf(c[nf][3] - mn1); rs1 += c[nf][3];
        }
        rs0 += __shfl_xor_sync(0xffffffffu, rs0, 1);
        rs0 += __shfl_xor_sync(0xffffffffu, rs0, 2);
        rs1 += __shfl_xor_sync(0xffffffffu, rs1, 1);
        rs1 += __shfl_xor_sync(0xffffffffu, rs1, 2);
        l0 = l0*cor0 + rs0;
        l1 = l1*cor1 + rs1;
#pragma unroll
        for (int dn = 0; dn < 8; dn++) {
            o[dn][0] *= cor0; o[dn][1] *= cor0;
            o[dn][2] *= cor1; o[dn][3] *= cor1;
        }

        // convert P to tf32 bits in place (only remaining in-loop conversion)
#pragma unroll
        for (int nf = 0; nf < 8; nf++)
#pragma unroll
            for (int j = 0; j < 4; j++)
                c[nf][j] = __uint_as_float(f2tf32(c[nf][j]));

        // ---- O += P V : convert C-frag -> A-frag via shuffles ----
        int src0 = (lane & ~3) | (tig >> 1);
        int src1 = src0 + 2;
        bool odd = (tig & 1);
#pragma unroll
        for (int kk = 0; kk < 8; kk++) {
            float f0 = __shfl_sync(0xffffffffu, c[kk][0], src0);
            float f1 = __shfl_sync(0xffffffffu, c[kk][1], src0);
            float f2 = __shfl_sync(0xffffffffu, c[kk][2], src0);
            float f3 = __shfl_sync(0xffffffffu, c[kk][3], src0);
            float h0 = __shfl_sync(0xffffffffu, c[kk][0], src1);
            float h1 = __shfl_sync(0xffffffffu, c[kk][1], src1);
            float h2 = __shfl_sync(0xffffffffu, c[kk][2], src1);
            float h3 = __shfl_sync(0xffffffffu, c[kk][3], src1);
            uint32_t a[4];
            a[0] = __float_as_uint(odd ? f1 : f0);  // (row gid,   col kk*8+tig)
            a[1] = __float_as_uint(odd ? f3 : f2);  // (row gid+8, col kk*8+tig)
            a[2] = __float_as_uint(odd ? h1 : h0);  // (row gid,   col kk*8+tig+4)
            a[3] = __float_as_uint(odd ? h3 : h2);  // (row gid+8, col kk*8+tig+4)
#pragma unroll
            for (int dn = 0; dn < 8; dn++) {
                uint32_t b[2];
                b[0] = __float_as_uint(Vb[(kk*8+tig  )*AP + dn*8 + gid]);
                b[1] = __float_as_uint(Vb[(kk*8+tig+4)*AP + dn*8 + gid]);
                mma_tf32(o[dn], a, b);
            }
        }
    }

    // ---- epilogue: write [B,T,H,dh] (== merged [B,T,D]) as tf32 bits ----
    float inv0 = 1.0f / l0, inv1 = 1.0f / l1;
    int bb = bh >> 4, h = bh & 15;
#pragma unroll
    for (int dn = 0; dn < 8; dn++) {
        int dd = dn*8 + 2*tig;
        size_t base0 = ((size_t)(bb*TT + r0g    )*HH + h)*DH + dd;
        size_t base1 = ((size_t)(bb*TT + r0g + 8)*HH + h)*DH + dd;
        g_A[base0]     = __uint_as_float(f2tf32(o[dn][0] * inv0));
        g_A[base0 + 1] = __uint_as_float(f2tf32(o[dn][1] * inv0));
        g_A[base1]     = __uint_as_float(f2tf32(o[dn][2] * inv1));
        g_A[base1 + 1] = __uint_as_float(f2tf32(o[dn][3] * inv1));
    }
}

// ---------------------------------------------------------------------------
extern "C" void kernel_launch(void* const* d_in, const int* in_sizes, int n_in,
                              void* d_out, int out_size) {
    const float* x      = (const float*)d_in[0];
    const float* W_attn = (const float*)d_in[1];
    const float* b_attn = (const float*)d_in[2];
    const float* W_proj = (const float*)d_in[3];
    const float* b_proj = (const float*)d_in[4];
    float* out = (float*)d_out;

    cudaFuncSetAttribute(gemm_tf32<3*DD, 1>,
                         cudaFuncAttributeMaxDynamicSharedMemorySize, GEMM_SMEM);
    cudaFuncSetAttribute(gemm_tf32<DD, 0>,
                         cudaFuncAttributeMaxDynamicSharedMemorySize, GEMM_SMEM);
    cudaFuncSetAttribute(attn_tc,
                         cudaFuncAttributeMaxDynamicSharedMemorySize, ATTN_SMEM);

    // Prep: convert inputs to tf32 bits (once; ~33MB traffic)
    {
        int nx = MROWS * DD;        // 4.19M
        int nw = DD * 3 * DD;       // 3.15M
        int np = DD * DD;           // 1.05M
        conv_tf32<0><<<(nx/4 + 255)/256, 256>>>(x, nx);
        conv_tf32<1><<<(nw/4 + 255)/256, 256>>>(W_attn, nw);
        conv_tf32<2><<<(np/4 + 255)/256, 256>>>(W_proj, np);
    }

    // QKV projection: grid (3072/128=24, 4096/128=32)
    gemm_tf32<3*DD, 1><<<dim3(24, 32), 256, GEMM_SMEM>>>(b_attn, nullptr);

    // Flash attention: grid (2048/128=16, 32)
    attn_tc<<<dim3(TT/128, BB*HH), 256, ATTN_SMEM>>>();

    // Output projection: grid (1024/128=8, 32)
    gemm_tf32<DD, 0><<<dim3(8, 32), 256, GEMM_SMEM>>>(b_proj, out);
}